// round 13
// baseline (speedup 1.0000x reference)
#include <cuda_runtime.h>
#include <math.h>

// DYAN FISTA sparse coding — parity-butterfly, 2 CTAs/SM.
//   x: [2,36,20480] f32; Drr/Dtheta: [40] f32; out: [2,161,20480] f32
//
// Round-13 vs round-12 (same math & schedule shape, doubled occupancy):
//  - CTA tile halved: 48 columns (NPAIR=24, SYS=26), SMEM 103.8 KB
//    -> 2 CTAs/SM. The two CTAs' phase schedules interleave, hiding each
//    other's barrier/LDS-latency bubbles (the round-12 limiter).
//  - 256 threads/CTA: phase 1 on 64 threads (2 warps), phase 2 on 246.

#define T36    36
#define TPAD   48
#define SAS    80      // float stride of atom matrix (40 cos | 40 sin)
#define NPAIR  24
#define NCOL   48
#define FDIM   20480
#define TOTCOL 40960
#define NITER  100
#define NTHREADS 256
#define SYS    26      // ull row stride (208B, 16B-aligned rows)
#define KOUT   161

typedef unsigned long long ull;

__device__ float g_A[T36 * SAS];   // normalized cos/sin atoms, t-major
__device__ float g_consts[2];      // {linv, lam}

// ---------------- packed f32x2 helpers ----------------
__device__ __forceinline__ void fma2(ull &d, ull a, ull b) {
    asm("fma.rn.f32x2 %0, %1, %2, %0;" : "+l"(d) : "l"(a), "l"(b));
}
__device__ __forceinline__ void add2(ull &d, ull a, ull b) {
    asm("add.rn.f32x2 %0, %1, %2;" : "=l"(d) : "l"(a), "l"(b));
}
__device__ __forceinline__ void mul2(ull &d, ull a, ull b) {
    asm("mul.rn.f32x2 %0, %1, %2;" : "=l"(d) : "l"(a), "l"(b));
}
__device__ __forceinline__ ull dup2(float x) {
    ull r; unsigned u = __float_as_uint(x);
    asm("mov.b64 %0, {%1, %1};" : "=l"(r) : "r"(u));
    return r;
}
__device__ __forceinline__ ull pack2(float a, float b) {
    ull r;
    asm("mov.b64 %0, {%1, %2};" : "=l"(r) : "f"(a), "f"(b));
    return r;
}
__device__ __forceinline__ float2 unpack2(ull v) {
    float2 r;
    asm("mov.b64 {%0, %1}, %2;" : "=f"(r.x), "=f"(r.y) : "l"(v));
    return r;
}

// =====================================================================
// Setup: normalized atoms + linv = 1/||D^T D||_F, lam = 0.1*linv
// =====================================================================
#define SETUP_T 256
#define KP 168
#define KREAL 161
__global__ void dyan_setup_kernel(const float* __restrict__ Drr,
                                  const float* __restrict__ Dtheta)
{
    __shared__ float  sDloc[T36 * KP];
    __shared__ double sred[SETUP_T];
    const int tid = threadIdx.x;

    for (int i = tid; i < T36 * KP; i += SETUP_T) sDloc[i] = 0.f;
    __syncthreads();

    for (int k = tid; k < KREAL; k += SETUP_T) {
        float col[T36];
        if (k == 0) {
            #pragma unroll
            for (int t = 0; t < T36; ++t) col[t] = 1.f;
        } else {
            const int grp = (k - 1) / 40;      // 0:rc 1:src 2:rs 3:srs
            const int nn  = (k - 1) % 40;
            const float r  = Drr[nn];
            const float th = Dtheta[nn];
            for (int t = 0; t < T36; ++t) {
                float ri   = powf(r, (float)t);
                float base = (grp < 2) ? cosf((float)t * th) : sinf((float)t * th);
                float v = ri * base;
                if ((grp & 1) && (t & 1)) v = -v;
                col[t] = v;
            }
        }
        float ss = 0.f;
        for (int t = 0; t < T36; ++t) ss += col[t] * col[t];
        float g = sqrtf(ss);
        if (g == 0.f) g = sqrtf((float)T36);
        for (int t = 0; t < T36; ++t) sDloc[t * KP + k] = col[t] / g;
    }
    __syncthreads();

    double acc = 0.0;
    for (int idx = tid; idx < KREAL * KREAL; idx += SETUP_T) {
        const int i = idx / KREAL, j = idx % KREAL;
        float d = 0.f;
        for (int t = 0; t < T36; ++t) d += sDloc[t * KP + i] * sDloc[t * KP + j];
        acc += (double)d * (double)d;
    }
    sred[tid] = acc;
    __syncthreads();
    for (int s = SETUP_T / 2; s > 0; s >>= 1) {
        if (tid < s) sred[tid] += sred[tid + s];
        __syncthreads();
    }
    if (tid == 0) {
        const float fro = (float)sqrt(sred[0]);
        g_consts[0] = 1.f / fro;
        g_consts[1] = 0.1f / fro;
    }
    // export normalized cos/sin atoms: g_A[t][n] = rc^, g_A[t][40+n] = rs^
    for (int i = tid; i < T36 * 40; i += SETUP_T) {
        const int t = i / 40, nn = i % 40;
        g_A[t * SAS + nn]      = sDloc[t * KP + 1 + nn];
        g_A[t * SAS + 40 + nn] = sDloc[t * KP + 81 + nn];
    }
}

// =====================================================================
// Main persistent FISTA kernel (butterfly, 2 CTAs/SM)
//   SMEM: sU[160][SYS] (p|q|m|n), sDtY[161][SYS], sV[48][SYS], sY0[SYS],
//         sA2[36][80] f32 (t-major), sA1[80][48] f32 (k-major parity-packed)
// =====================================================================
__global__ void __launch_bounds__(NTHREADS, 2)
dyan_fista_kernel(const float* __restrict__ x, float* __restrict__ out)
{
    extern __shared__ unsigned char smraw[];
    ull*   sU   = (ull*)smraw;              // 160*SYS
    ull*   sDtY = sU   + 160 * SYS;         // 161*SYS
    ull*   sV   = sDtY + 161 * SYS;         // 48*SYS
    ull*   sY0  = sV   + TPAD * SYS;        // SYS
    float* sA2  = (float*)(sY0 + SYS);      // 36*80
    float* sA1  = sA2 + T36 * SAS;          // 80*48

    const int tid     = threadIdx.x;
    const int colBase = blockIdx.x * NCOL;
    const float linv = g_consts[0];
    const float lam  = g_consts[1];
    const float invs = 1.0f / 6.0f;
    const ull  neg1   = dup2(-1.f);
    const ull  half2  = dup2(0.5f);
    const ull  invs2  = dup2(invs);
    const ull  nlinv2 = dup2(-linv);

    // ---- stage atoms (both layouts) ----
    for (int i = tid; i < T36 * SAS; i += NTHREADS) sA2[i] = g_A[i];
    for (int i = tid; i < SAS * 48; i += NTHREADS) {
        const int kk = i / 48, c = i % 48;
        const int P = c / 24, j = c % 24;
        const int t = 2 * j + P;
        sA1[i] = (t < T36) ? g_A[t * SAS + kk] : 0.f;
    }
    // ---- load Y into sV rows 0..35, zero pad rows ----
    for (int i = tid; i < TPAD * NPAIR; i += NTHREADS) {
        const int t = i / NPAIR, p = i % NPAIR;
        ull v = 0ull;
        const int c0 = colBase + 2 * p;
        if (t < T36 && c0 < TOTCOL) {
            const int b = c0 / FDIM, f = c0 % FDIM;
            const float2 yv = *(const float2*)(x + ((size_t)b * T36 + t) * FDIM + f);
            v = pack2(yv.x, yv.y);
        }
        sV[t * SYS + p] = v;
    }
    for (int i = tid; i < 160 * SYS; i += NTHREADS) sU[i] = 0ull;
    if (tid < SYS) sY0[tid] = 0ull;
    __syncthreads();

    // ---- phase-2 thread mapping (warp-broadcast v loads) ----
    const int  ng   = tid % 41;           // 0..39 atom-pairs, 40 = k0
    const int  pg   = tid / 41;           // 0..6; active < 6 (4 ull each)
    const bool act  = (pg < 6);
    const bool reg2 = act && (ng < 40);
    const bool isK0 = act && (ng == 40);
    const float* aP = sA2 + 2 * ng;
    const ull*   vP = sV + 4 * pg;

    // ---- DtY init (sV holds Y) ----
    if (reg2) {
        ull E[2][4] = {}, O[2][4] = {};
        #pragma unroll 6
        for (int tb = 0; tb < T36; tb += 2) {
            {   const float2 a = *(const float2*)(aP + tb * SAS);
                const ulonglong2 v01 = *(const ulonglong2*)(vP + tb * SYS);
                const ulonglong2 v23 = *(const ulonglong2*)(vP + tb * SYS + 2);
                const ull a0 = dup2(a.x), a1 = dup2(a.y);
                fma2(E[0][0],a0,v01.x); fma2(E[0][1],a0,v01.y); fma2(E[0][2],a0,v23.x); fma2(E[0][3],a0,v23.y);
                fma2(E[1][0],a1,v01.x); fma2(E[1][1],a1,v01.y); fma2(E[1][2],a1,v23.x); fma2(E[1][3],a1,v23.y);
            }
            {   const float2 a = *(const float2*)(aP + (tb+1) * SAS);
                const ulonglong2 v01 = *(const ulonglong2*)(vP + (tb+1) * SYS);
                const ulonglong2 v23 = *(const ulonglong2*)(vP + (tb+1) * SYS + 2);
                const ull a0 = dup2(a.x), a1 = dup2(a.y);
                fma2(O[0][0],a0,v01.x); fma2(O[0][1],a0,v01.y); fma2(O[0][2],a0,v23.x); fma2(O[0][3],a0,v23.y);
                fma2(O[1][0],a1,v01.x); fma2(O[1][1],a1,v01.y); fma2(O[1][2],a1,v23.x); fma2(O[1][3],a1,v23.y);
            }
        }
        const ull linv2 = dup2(linv);
        #pragma unroll
        for (int s = 0; s < 2; ++s) {
            const int slot = 2 * ng + s;
            const int ka = (slot < 40) ? 1 + slot : 41 + slot;
            const int kb = ka + 40;
            ull* da = sDtY + (size_t)ka * SYS + 4 * pg;
            ull* db = sDtY + (size_t)kb * SYS + 4 * pg;
            #pragma unroll
            for (int j = 0; j < 4; ++j) {
                ull Sa; add2(Sa, E[s][j], O[s][j]); mul2(Sa, Sa, linv2); da[j] = Sa;
                ull Sb = E[s][j]; fma2(Sb, neg1, O[s][j]); mul2(Sb, Sb, linv2); db[j] = Sb;
            }
        }
    } else if (isK0) {
        ull T[4] = {};
        #pragma unroll 6
        for (int t = 0; t < T36; ++t) {
            const ulonglong2 v01 = *(const ulonglong2*)(vP + t * SYS);
            const ulonglong2 v23 = *(const ulonglong2*)(vP + t * SYS + 2);
            add2(T[0], T[0], v01.x); add2(T[1], T[1], v01.y);
            add2(T[2], T[2], v23.x); add2(T[3], T[3], v23.y);
        }
        const ull sc = dup2(invs * linv);
        ull* d0 = sDtY + 4 * pg;
        #pragma unroll
        for (int j = 0; j < 4; ++j) { ull s; mul2(s, T[j], sc); d0[j] = s; }
    }

    // ---- persistent state ----
    ull xold[2][2][4] = {};        // reg2: [s][a/b][j]
    ull x0r[4] = {}, y0r[4] = {};  // k0
    float tcur = 1.f;

    // ---- phase-1 mapping: 64 threads (2 warps), single-parity per G ----
    //   lane = 8 tg x 4 cg; G = 8*wp + tg in 0..15; P = G/8; g = G%8;
    //   rows j = 3g..3g+2 (parity rows, t = 2j+P), cols 6 ull at 6*cg.
    const int  wp    = tid >> 5;
    const int  ln    = tid & 31;
    const int  cg1   = ln & 3;
    const int  tg1   = ln >> 2;
    const bool p1act = (tid < 64);
    const int  G     = 8 * wp + tg1;
    const int  P1    = G >> 3;
    const int  j0    = 3 * (G & 7);

    __syncthreads();

    for (int it = 0; it < NITER; ++it) {
        // ========== phase 1: V = butterfly(D) @ u ==========
        if (p1act) {
            ull vac[3][6];
            {   // init with ones-column contribution (sY0 = y0/6, momentum state)
                const ull* yp = sY0 + 6 * cg1;
                const ulonglong2 y01 = *(const ulonglong2*)(yp);
                const ulonglong2 y23 = *(const ulonglong2*)(yp + 2);
                const ulonglong2 y45 = *(const ulonglong2*)(yp + 4);
                #pragma unroll
                for (int r = 0; r < 3; ++r) {
                    vac[r][0] = y01.x; vac[r][1] = y01.y;
                    vac[r][2] = y23.x; vac[r][3] = y23.y;
                    vac[r][4] = y45.x; vac[r][5] = y45.y;
                }
            }
            const float* a1p = sA1 + P1 * 24 + j0;
            const ull*   ub  = sU + (size_t)(P1 * 80) * SYS + 6 * cg1;
            #pragma unroll 4
            for (int kk = 0; kk < 80; ++kk) {
                const float* ak = a1p + kk * 48;
                const ull d0 = dup2(ak[0]);
                const ull d1 = dup2(ak[1]);
                const ull d2 = dup2(ak[2]);
                const ull* ur = ub + (size_t)kk * SYS;
                const ulonglong2 u01 = *(const ulonglong2*)(ur);
                const ulonglong2 u23 = *(const ulonglong2*)(ur + 2);
                const ulonglong2 u45 = *(const ulonglong2*)(ur + 4);
                fma2(vac[0][0],d0,u01.x); fma2(vac[0][1],d0,u01.y);
                fma2(vac[0][2],d0,u23.x); fma2(vac[0][3],d0,u23.y);
                fma2(vac[0][4],d0,u45.x); fma2(vac[0][5],d0,u45.y);
                fma2(vac[1][0],d1,u01.x); fma2(vac[1][1],d1,u01.y);
                fma2(vac[1][2],d1,u23.x); fma2(vac[1][3],d1,u23.y);
                fma2(vac[1][4],d1,u45.x); fma2(vac[1][5],d1,u45.y);
                fma2(vac[2][0],d2,u01.x); fma2(vac[2][1],d2,u01.y);
                fma2(vac[2][2],d2,u23.x); fma2(vac[2][3],d2,u23.y);
                fma2(vac[2][4],d2,u45.x); fma2(vac[2][5],d2,u45.y);
            }
            #pragma unroll
            for (int r = 0; r < 3; ++r) {
                const int t = 2 * (j0 + r) + P1;
                ull* vr = sV + (size_t)t * SYS + 6 * cg1;
                ulonglong2 w01; w01.x = vac[r][0]; w01.y = vac[r][1];
                ulonglong2 w23; w23.x = vac[r][2]; w23.y = vac[r][3];
                ulonglong2 w45; w45.x = vac[r][4]; w45.y = vac[r][5];
                *(ulonglong2*)(vr)     = w01;
                *(ulonglong2*)(vr + 2) = w23;
                *(ulonglong2*)(vr + 4) = w45;
            }
        }
        __syncthreads();

        const float tnext = 0.5f * (1.f + sqrtf(fmaf(4.f * tcur, tcur, 1.f)));
        const float tt = (tcur - 1.f) / tnext;
        tcur = tnext;

        // ========== phase 2: E/O sums + fused epilogue ==========
        if (reg2) {
            ull E[2][4] = {}, O[2][4] = {};
            #pragma unroll 6
            for (int tb = 0; tb < T36; tb += 2) {
                {   const float2 a = *(const float2*)(aP + tb * SAS);
                    const ulonglong2 v01 = *(const ulonglong2*)(vP + tb * SYS);
                    const ulonglong2 v23 = *(const ulonglong2*)(vP + tb * SYS + 2);
                    const ull a0 = dup2(a.x), a1 = dup2(a.y);
                    fma2(E[0][0],a0,v01.x); fma2(E[0][1],a0,v01.y); fma2(E[0][2],a0,v23.x); fma2(E[0][3],a0,v23.y);
                    fma2(E[1][0],a1,v01.x); fma2(E[1][1],a1,v01.y); fma2(E[1][2],a1,v23.x); fma2(E[1][3],a1,v23.y);
                }
                {   const float2 a = *(const float2*)(aP + (tb+1) * SAS);
                    const ulonglong2 v01 = *(const ulonglong2*)(vP + (tb+1) * SYS);
                    const ulonglong2 v23 = *(const ulonglong2*)(vP + (tb+1) * SYS + 2);
                    const ull a0 = dup2(a.x), a1 = dup2(a.y);
                    fma2(O[0][0],a0,v01.x); fma2(O[0][1],a0,v01.y); fma2(O[0][2],a0,v23.x); fma2(O[0][3],a0,v23.y);
                    fma2(O[1][0],a1,v01.x); fma2(O[1][1],a1,v01.y); fma2(O[1][2],a1,v23.x); fma2(O[1][3],a1,v23.y);
                }
            }
            #pragma unroll
            for (int s = 0; s < 2; ++s) {
                const int slot = 2 * ng + s;
                const int ka = (slot < 40) ? 1 + slot : 41 + slot;
                const int kb = ka + 40;
                ull* Uprow = sU + (size_t)slot * SYS + 4 * pg;
                ull* Umrow = sU + (size_t)(80 + slot) * SYS + 4 * pg;
                const ull* Da = sDtY + (size_t)ka * SYS + 4 * pg;
                const ull* Db = sDtY + (size_t)kb * SYS + 4 * pg;
                ull pnew[4], mnew[4];
                #pragma unroll
                for (int j = 0; j < 4; ++j) {
                    const ull up = Uprow[j], um = Umrow[j];
                    ull ya; add2(ya, up, um); mul2(ya, ya, half2);        // y_a = (p+m)/2
                    ull yb = up; fma2(yb, neg1, um); mul2(yb, yb, half2); // y_b = (p-m)/2
                    ull Sa; add2(Sa, E[s][j], O[s][j]);
                    ull Sb = E[s][j]; fma2(Sb, neg1, O[s][j]);
                    ull ra = ya; fma2(ra, nlinv2, Sa); add2(ra, ra, Da[j]);
                    ull rb = yb; fma2(rb, nlinv2, Sb); add2(rb, rb, Db[j]);
                    const float2 fa = unpack2(ra);
                    const float xa0 = copysignf(fmaxf(fabsf(fa.x) - lam, 0.f), fa.x);
                    const float xa1 = copysignf(fmaxf(fabsf(fa.y) - lam, 0.f), fa.y);
                    const float2 xoa = unpack2(xold[s][0][j]);
                    const float yna0 = fmaf(tt, xa0 - xoa.x, xa0);
                    const float yna1 = fmaf(tt, xa1 - xoa.y, xa1);
                    xold[s][0][j] = pack2(xa0, xa1);
                    const ull yna = pack2(yna0, yna1);
                    const float2 fb = unpack2(rb);
                    const float xb0 = copysignf(fmaxf(fabsf(fb.x) - lam, 0.f), fb.x);
                    const float xb1 = copysignf(fmaxf(fabsf(fb.y) - lam, 0.f), fb.y);
                    const float2 xob = unpack2(xold[s][1][j]);
                    const float ynb0 = fmaf(tt, xb0 - xob.x, xb0);
                    const float ynb1 = fmaf(tt, xb1 - xob.y, xb1);
                    xold[s][1][j] = pack2(xb0, xb1);
                    const ull ynb = pack2(ynb0, ynb1);
                    add2(pnew[j], yna, ynb);
                    mnew[j] = yna; fma2(mnew[j], neg1, ynb);
                }
                ulonglong2 p01; p01.x = pnew[0]; p01.y = pnew[1];
                ulonglong2 p23; p23.x = pnew[2]; p23.y = pnew[3];
                *(ulonglong2*)(Uprow)     = p01;
                *(ulonglong2*)(Uprow + 2) = p23;
                ulonglong2 m01; m01.x = mnew[0]; m01.y = mnew[1];
                ulonglong2 m23; m23.x = mnew[2]; m23.y = mnew[3];
                *(ulonglong2*)(Umrow)     = m01;
                *(ulonglong2*)(Umrow + 2) = m23;
            }
        } else if (isK0) {
            ull T[4] = {};
            #pragma unroll 6
            for (int t = 0; t < T36; ++t) {
                const ulonglong2 v01 = *(const ulonglong2*)(vP + t * SYS);
                const ulonglong2 v23 = *(const ulonglong2*)(vP + t * SYS + 2);
                add2(T[0], T[0], v01.x); add2(T[1], T[1], v01.y);
                add2(T[2], T[2], v23.x); add2(T[3], T[3], v23.y);
            }
            const ull* D0 = sDtY + 4 * pg;
            #pragma unroll
            for (int j = 0; j < 4; ++j) {
                ull S; mul2(S, T[j], invs2);
                ull r = y0r[j]; fma2(r, nlinv2, S); add2(r, r, D0[j]);
                const float2 fr = unpack2(r);
                const float x0 = copysignf(fmaxf(fabsf(fr.x) - lam, 0.f), fr.x);
                const float x1 = copysignf(fmaxf(fabsf(fr.y) - lam, 0.f), fr.y);
                const float2 xo = unpack2(x0r[j]);
                const float yn0 = fmaf(tt, x0 - xo.x, x0);
                const float yn1 = fmaf(tt, x1 - xo.y, x1);
                x0r[j] = pack2(x0, x1);
                y0r[j] = pack2(yn0, yn1);
                ull ys; mul2(ys, y0r[j], invs2);
                sY0[4 * pg + j] = ys;
            }
        }
        __syncthreads();
    }

    // ---- write final x (xold) straight to GMEM ----
    if (reg2) {
        #pragma unroll
        for (int s = 0; s < 2; ++s) {
            const int slot = 2 * ng + s;
            const int ka = (slot < 40) ? 1 + slot : 41 + slot;
            const int kb = ka + 40;
            #pragma unroll
            for (int j = 0; j < 4; ++j) {
                const int c0 = colBase + 8 * pg + 2 * j;
                if (c0 < TOTCOL) {
                    const int b = c0 / FDIM, f = c0 % FDIM;
                    *(float2*)(out + ((size_t)b * KOUT + ka) * FDIM + f) = unpack2(xold[s][0][j]);
                    *(float2*)(out + ((size_t)b * KOUT + kb) * FDIM + f) = unpack2(xold[s][1][j]);
                }
            }
        }
    } else if (isK0) {
        #pragma unroll
        for (int j = 0; j < 4; ++j) {
            const int c0 = colBase + 8 * pg + 2 * j;
            if (c0 < TOTCOL) {
                const int b = c0 / FDIM, f = c0 % FDIM;
                *(float2*)(out + ((size_t)b * KOUT + 0) * FDIM + f) = unpack2(x0r[j]);
            }
        }
    }
}

// =====================================================================
extern "C" void kernel_launch(void* const* d_in, const int* in_sizes, int n_in,
                              void* d_out, int out_size)
{
    const float* x   = (const float*)d_in[0];
    const float* drr = (const float*)d_in[1];
    const float* dth = (const float*)d_in[2];
    float* out = (float*)d_out;
    (void)in_sizes; (void)n_in; (void)out_size;

    const size_t smem = (size_t)(160 * SYS + 161 * SYS + TPAD * SYS + SYS) * sizeof(ull)
                      + (size_t)(T36 * SAS + SAS * 48) * sizeof(float);   // 103,840 B

    cudaFuncSetAttribute(dyan_fista_kernel,
                         cudaFuncAttributeMaxDynamicSharedMemorySize, (int)smem);

    dyan_setup_kernel<<<1, SETUP_T>>>(drr, dth);

    const int grid = (TOTCOL + NCOL - 1) / NCOL;   // 854
    dyan_fista_kernel<<<grid, NTHREADS, smem>>>(x, out);
}

// round 16
// speedup vs baseline: 1.1381x; 1.1381x over previous
#include <cuda_runtime.h>
#include <math.h>

// DYAN FISTA sparse coding — parity-butterfly, conflict-free epilogue.
//   x: [2,36,20480] f32; Drr/Dtheta: [40] f32; out: [2,161,20480] f32
//
// Round-14 = round-12 (best: 2455us) + two layout-only changes:
//  - U and DtY rows PERMUTED so the epilogue's lane step is 1 physical row
//    (quad-bank step 25 mod 8 = 1 -> conflict-free; was 8-way conflicted at
//    lane step 2 rows). Phase 1 reads U rows in permuted order with a
//    matching permuted atom table sA1d.
//  - phase-1 atom table pre-duplicated as ull (broadcast loads, 1 wf) to
//    remove dup-MOVs from the latency-bound phase-1 warps.

#define T36    36
#define TPAD   48
#define SAS    80      // float stride of atom matrix (40 cos | 40 sin)
#define NPAIR  48
#define NCOL   96
#define FDIM   20480
#define TOTCOL 40960
#define NITER  100
#define NTHREADS 512
#define SYS    50      // ull row stride (400B, 16B-aligned rows)
#define KOUT   161

typedef unsigned long long ull;

__device__ float g_A[T36 * SAS];   // normalized cos/sin atoms, t-major
__device__ float g_consts[2];      // {linv, lam}

// ---------------- packed f32x2 helpers ----------------
__device__ __forceinline__ void fma2(ull &d, ull a, ull b) {
    asm("fma.rn.f32x2 %0, %1, %2, %0;" : "+l"(d) : "l"(a), "l"(b));
}
__device__ __forceinline__ void add2(ull &d, ull a, ull b) {
    asm("add.rn.f32x2 %0, %1, %2;" : "=l"(d) : "l"(a), "l"(b));
}
__device__ __forceinline__ void mul2(ull &d, ull a, ull b) {
    asm("mul.rn.f32x2 %0, %1, %2;" : "=l"(d) : "l"(a), "l"(b));
}
__device__ __forceinline__ ull dup2(float x) {
    ull r; unsigned u = __float_as_uint(x);
    asm("mov.b64 %0, {%1, %1};" : "=l"(r) : "r"(u));
    return r;
}
__device__ __forceinline__ ull pack2(float a, float b) {
    ull r;
    asm("mov.b64 %0, {%1, %2};" : "=l"(r) : "f"(a), "f"(b));
    return r;
}
__device__ __forceinline__ float2 unpack2(ull v) {
    float2 r;
    asm("mov.b64 {%0, %1}, %2;" : "=f"(r.x), "=f"(r.y) : "l"(v));
    return r;
}

// =====================================================================
// Setup: normalized atoms + linv = 1/||D^T D||_F, lam = 0.1*linv
// =====================================================================
#define SETUP_T 256
#define KP 168
#define KREAL 161
__global__ void dyan_setup_kernel(const float* __restrict__ Drr,
                                  const float* __restrict__ Dtheta)
{
    __shared__ float  sDloc[T36 * KP];
    __shared__ double sred[SETUP_T];
    const int tid = threadIdx.x;

    for (int i = tid; i < T36 * KP; i += SETUP_T) sDloc[i] = 0.f;
    __syncthreads();

    for (int k = tid; k < KREAL; k += SETUP_T) {
        float col[T36];
        if (k == 0) {
            #pragma unroll
            for (int t = 0; t < T36; ++t) col[t] = 1.f;
        } else {
            const int grp = (k - 1) / 40;      // 0:rc 1:src 2:rs 3:srs
            const int nn  = (k - 1) % 40;
            const float r  = Drr[nn];
            const float th = Dtheta[nn];
            for (int t = 0; t < T36; ++t) {
                float ri   = powf(r, (float)t);
                float base = (grp < 2) ? cosf((float)t * th) : sinf((float)t * th);
                float v = ri * base;
                if ((grp & 1) && (t & 1)) v = -v;
                col[t] = v;
            }
        }
        float ss = 0.f;
        for (int t = 0; t < T36; ++t) ss += col[t] * col[t];
        float g = sqrtf(ss);
        if (g == 0.f) g = sqrtf((float)T36);
        for (int t = 0; t < T36; ++t) sDloc[t * KP + k] = col[t] / g;
    }
    __syncthreads();

    double acc = 0.0;
    for (int idx = tid; idx < KREAL * KREAL; idx += SETUP_T) {
        const int i = idx / KREAL, j = idx % KREAL;
        float d = 0.f;
        for (int t = 0; t < T36; ++t) d += sDloc[t * KP + i] * sDloc[t * KP + j];
        acc += (double)d * (double)d;
    }
    sred[tid] = acc;
    __syncthreads();
    for (int s = SETUP_T / 2; s > 0; s >>= 1) {
        if (tid < s) sred[tid] += sred[tid + s];
        __syncthreads();
    }
    if (tid == 0) {
        const float fro = (float)sqrt(sred[0]);
        g_consts[0] = 1.f / fro;
        g_consts[1] = 0.1f / fro;
    }
    // export normalized cos/sin atoms: g_A[t][n] = rc^, g_A[t][40+n] = rs^
    for (int i = tid; i < T36 * 40; i += SETUP_T) {
        const int t = i / 40, nn = i % 40;
        g_A[t * SAS + nn]      = sDloc[t * KP + 1 + nn];
        g_A[t * SAS + 40 + nn] = sDloc[t * KP + 81 + nn];
    }
}

// =====================================================================
// Main persistent FISTA kernel (butterfly, permuted layouts)
//   Physical U row for logical slot (atom a = 2ng+s): r = s*40+ng.
//   sigma(r) = (r<40) ? 2r : 2(r-40)+1  (atom index at phys row r).
//   SMEM: sU[160][SYS] (pq rows 0..79 | mn rows 80..159), sDtY[161][SYS]
//   (k>=1 at ab*80 + s*40 + ng; k0 at row 160), sV[48][SYS], sY0[SYS],
//   sA2[36][80] f32 (t-major, phase 2), sA1d[80][48] ull (phase 1,
//   phys-row-major, parity-packed cols, pre-duplicated).
// =====================================================================
__global__ void __launch_bounds__(NTHREADS, 1)
dyan_fista_kernel(const float* __restrict__ x, float* __restrict__ out)
{
    extern __shared__ unsigned char smraw[];
    ull*   sU   = (ull*)smraw;              // 160*SYS
    ull*   sDtY = sU   + 160 * SYS;         // 161*SYS
    ull*   sV   = sDtY + 161 * SYS;         // 48*SYS
    ull*   sY0  = sV   + TPAD * SYS;        // SYS
    ull*   sA1d = sY0  + SYS;               // 80*48 ull
    float* sA2  = (float*)(sA1d + SAS * 48); // 36*80 f32

    const int tid     = threadIdx.x;
    const int colBase = blockIdx.x * NCOL;
    const float linv = g_consts[0];
    const float lam  = g_consts[1];
    const float invs = 1.0f / 6.0f;
    const ull  neg1   = dup2(-1.f);
    const ull  half2  = dup2(0.5f);
    const ull  invs2  = dup2(invs);
    const ull  nlinv2 = dup2(-linv);

    // ---- stage atoms (both layouts) ----
    for (int i = tid; i < T36 * SAS; i += NTHREADS) sA2[i] = g_A[i];
    for (int i = tid; i < SAS * 48; i += NTHREADS) {
        const int r = i / 48, c = i % 48;
        const int P = c / 24, j = c % 24;
        const int t = 2 * j + P;
        const int slot = (r < 40) ? 2 * r : 2 * (r - 40) + 1;   // sigma(r)
        sA1d[i] = (t < T36) ? dup2(g_A[t * SAS + slot]) : 0ull;
    }
    // ---- load Y into sV rows 0..35, zero pad rows ----
    for (int i = tid; i < TPAD * NPAIR; i += NTHREADS) {
        const int t = i / NPAIR, p = i % NPAIR;
        ull v = 0ull;
        const int c0 = colBase + 2 * p;
        if (t < T36 && c0 < TOTCOL) {
            const int b = c0 / FDIM, f = c0 % FDIM;
            const float2 yv = *(const float2*)(x + ((size_t)b * T36 + t) * FDIM + f);
            v = pack2(yv.x, yv.y);
        }
        sV[t * SYS + p] = v;
    }
    for (int i = tid; i < 160 * SYS; i += NTHREADS) sU[i] = 0ull;
    if (tid < SYS) sY0[tid] = 0ull;
    __syncthreads();

    // ---- phase-2 thread mapping (warp-broadcast v loads) ----
    const int  ng   = tid % 41;           // 0..39 atom-pairs, 40 = k0
    const int  pg   = tid / 41;           // 0..12; active < 12 (4 ull each)
    const bool act  = (pg < 12);
    const bool reg2 = act && (ng < 40);
    const bool isK0 = act && (ng == 40);
    const float* aP = sA2 + 2 * ng;
    const ull*   vP = sV + 4 * pg;

    // ---- DtY init (sV holds Y) ----
    if (reg2) {
        ull E[2][4] = {}, O[2][4] = {};
        #pragma unroll 6
        for (int tb = 0; tb < T36; tb += 2) {
            {   const float2 a = *(const float2*)(aP + tb * SAS);
                const ulonglong2 v01 = *(const ulonglong2*)(vP + tb * SYS);
                const ulonglong2 v23 = *(const ulonglong2*)(vP + tb * SYS + 2);
                const ull a0 = dup2(a.x), a1 = dup2(a.y);
                fma2(E[0][0],a0,v01.x); fma2(E[0][1],a0,v01.y); fma2(E[0][2],a0,v23.x); fma2(E[0][3],a0,v23.y);
                fma2(E[1][0],a1,v01.x); fma2(E[1][1],a1,v01.y); fma2(E[1][2],a1,v23.x); fma2(E[1][3],a1,v23.y);
            }
            {   const float2 a = *(const float2*)(aP + (tb+1) * SAS);
                const ulonglong2 v01 = *(const ulonglong2*)(vP + (tb+1) * SYS);
                const ulonglong2 v23 = *(const ulonglong2*)(vP + (tb+1) * SYS + 2);
                const ull a0 = dup2(a.x), a1 = dup2(a.y);
                fma2(O[0][0],a0,v01.x); fma2(O[0][1],a0,v01.y); fma2(O[0][2],a0,v23.x); fma2(O[0][3],a0,v23.y);
                fma2(O[1][0],a1,v01.x); fma2(O[1][1],a1,v01.y); fma2(O[1][2],a1,v23.x); fma2(O[1][3],a1,v23.y);
            }
        }
        const ull linv2 = dup2(linv);
        #pragma unroll
        for (int s = 0; s < 2; ++s) {
            const int pr = s * 40 + ng;                 // permuted row
            ull* da = sDtY + (size_t)pr * SYS + 4 * pg;         // ab=0
            ull* db = sDtY + (size_t)(80 + pr) * SYS + 4 * pg;  // ab=1
            #pragma unroll
            for (int j = 0; j < 4; ++j) {
                ull Sa; add2(Sa, E[s][j], O[s][j]); mul2(Sa, Sa, linv2); da[j] = Sa;
                ull Sb = E[s][j]; fma2(Sb, neg1, O[s][j]); mul2(Sb, Sb, linv2); db[j] = Sb;
            }
        }
    } else if (isK0) {
        ull T[4] = {};
        #pragma unroll 6
        for (int t = 0; t < T36; ++t) {
            const ulonglong2 v01 = *(const ulonglong2*)(vP + t * SYS);
            const ulonglong2 v23 = *(const ulonglong2*)(vP + t * SYS + 2);
            add2(T[0], T[0], v01.x); add2(T[1], T[1], v01.y);
            add2(T[2], T[2], v23.x); add2(T[3], T[3], v23.y);
        }
        const ull sc = dup2(invs * linv);
        ull* d0 = sDtY + (size_t)160 * SYS + 4 * pg;
        #pragma unroll
        for (int j = 0; j < 4; ++j) { ull s; mul2(s, T[j], sc); d0[j] = s; }
    }

    // ---- persistent state ----
    ull xold[2][2][4] = {};        // reg2: [s][a/b][j]
    ull x0r[4] = {}, y0r[4] = {};  // k0
    float tcur = 1.f;

    // ---- phase-1 mapping: 128 threads, 1 warp/SMSP, single-parity warps ----
    const int  wp    = tid >> 5;
    const int  ln    = tid & 31;
    const int  cg1   = ln & 7;
    const int  tg1   = ln >> 3;
    const bool p1act = (tid < 128);
    const int  G     = 4 * wp + tg1;
    const int  P1    = G >> 3;
    const int  j0    = 3 * (G & 7);

    __syncthreads();

    for (int it = 0; it < NITER; ++it) {
        // ========== phase 1: V = butterfly(D) @ u (permuted rows) ==========
        if (p1act) {
            ull vac[3][6];
            {   // init with ones-column contribution (sY0 = y0/6, momentum state)
                const ull* yp = sY0 + 6 * cg1;
                const ulonglong2 y01 = *(const ulonglong2*)(yp);
                const ulonglong2 y23 = *(const ulonglong2*)(yp + 2);
                const ulonglong2 y45 = *(const ulonglong2*)(yp + 4);
                #pragma unroll
                for (int r = 0; r < 3; ++r) {
                    vac[r][0] = y01.x; vac[r][1] = y01.y;
                    vac[r][2] = y23.x; vac[r][3] = y23.y;
                    vac[r][4] = y45.x; vac[r][5] = y45.y;
                }
            }
            const ull* a1p = sA1d + P1 * 24 + j0;
            const ull* ub  = sU + (size_t)(P1 * 80) * SYS + 6 * cg1;
            #pragma unroll 4
            for (int kk = 0; kk < 80; ++kk) {
                const ull* ak = a1p + kk * 48;
                const ull d0 = ak[0];
                const ull d1 = ak[1];
                const ull d2 = ak[2];
                const ull* ur = ub + (size_t)kk * SYS;
                const ulonglong2 u01 = *(const ulonglong2*)(ur);
                const ulonglong2 u23 = *(const ulonglong2*)(ur + 2);
                const ulonglong2 u45 = *(const ulonglong2*)(ur + 4);
                fma2(vac[0][0],d0,u01.x); fma2(vac[0][1],d0,u01.y);
                fma2(vac[0][2],d0,u23.x); fma2(vac[0][3],d0,u23.y);
                fma2(vac[0][4],d0,u45.x); fma2(vac[0][5],d0,u45.y);
                fma2(vac[1][0],d1,u01.x); fma2(vac[1][1],d1,u01.y);
                fma2(vac[1][2],d1,u23.x); fma2(vac[1][3],d1,u23.y);
                fma2(vac[1][4],d1,u45.x); fma2(vac[1][5],d1,u45.y);
                fma2(vac[2][0],d2,u01.x); fma2(vac[2][1],d2,u01.y);
                fma2(vac[2][2],d2,u23.x); fma2(vac[2][3],d2,u23.y);
                fma2(vac[2][4],d2,u45.x); fma2(vac[2][5],d2,u45.y);
            }
            #pragma unroll
            for (int r = 0; r < 3; ++r) {
                const int t = 2 * (j0 + r) + P1;
                ull* vr = sV + (size_t)t * SYS + 6 * cg1;
                ulonglong2 w01; w01.x = vac[r][0]; w01.y = vac[r][1];
                ulonglong2 w23; w23.x = vac[r][2]; w23.y = vac[r][3];
                ulonglong2 w45; w45.x = vac[r][4]; w45.y = vac[r][5];
                *(ulonglong2*)(vr)     = w01;
                *(ulonglong2*)(vr + 2) = w23;
                *(ulonglong2*)(vr + 4) = w45;
            }
        }
        __syncthreads();

        const float tnext = 0.5f * (1.f + sqrtf(fmaf(4.f * tcur, tcur, 1.f)));
        const float tt = (tcur - 1.f) / tnext;
        tcur = tnext;

        // ========== phase 2: E/O sums + fused epilogue (conflict-free) ==========
        if (reg2) {
            ull E[2][4] = {}, O[2][4] = {};
            #pragma unroll 6
            for (int tb = 0; tb < T36; tb += 2) {
                {   const float2 a = *(const float2*)(aP + tb * SAS);
                    const ulonglong2 v01 = *(const ulonglong2*)(vP + tb * SYS);
                    const ulonglong2 v23 = *(const ulonglong2*)(vP + tb * SYS + 2);
                    const ull a0 = dup2(a.x), a1 = dup2(a.y);
                    fma2(E[0][0],a0,v01.x); fma2(E[0][1],a0,v01.y); fma2(E[0][2],a0,v23.x); fma2(E[0][3],a0,v23.y);
                    fma2(E[1][0],a1,v01.x); fma2(E[1][1],a1,v01.y); fma2(E[1][2],a1,v23.x); fma2(E[1][3],a1,v23.y);
                }
                {   const float2 a = *(const float2*)(aP + (tb+1) * SAS);
                    const ulonglong2 v01 = *(const ulonglong2*)(vP + (tb+1) * SYS);
                    const ulonglong2 v23 = *(const ulonglong2*)(vP + (tb+1) * SYS + 2);
                    const ull a0 = dup2(a.x), a1 = dup2(a.y);
                    fma2(O[0][0],a0,v01.x); fma2(O[0][1],a0,v01.y); fma2(O[0][2],a0,v23.x); fma2(O[0][3],a0,v23.y);
                    fma2(O[1][0],a1,v01.x); fma2(O[1][1],a1,v01.y); fma2(O[1][2],a1,v23.x); fma2(O[1][3],a1,v23.y);
                }
            }
            #pragma unroll
            for (int s = 0; s < 2; ++s) {
                const int pr = s * 40 + ng;                 // permuted row
                ull* Uprow = sU + (size_t)pr * SYS + 4 * pg;
                ull* Umrow = sU + (size_t)(80 + pr) * SYS + 4 * pg;
                const ull* Da = sDtY + (size_t)pr * SYS + 4 * pg;
                const ull* Db = sDtY + (size_t)(80 + pr) * SYS + 4 * pg;
                ull pnew[4], mnew[4];
                #pragma unroll
                for (int j = 0; j < 4; ++j) {
                    const ull up = Uprow[j], um = Umrow[j];
                    ull ya; add2(ya, up, um); mul2(ya, ya, half2);        // y_a = (p+m)/2
                    ull yb = up; fma2(yb, neg1, um); mul2(yb, yb, half2); // y_b = (p-m)/2
                    ull Sa; add2(Sa, E[s][j], O[s][j]);
                    ull Sb = E[s][j]; fma2(Sb, neg1, O[s][j]);
                    ull ra = ya; fma2(ra, nlinv2, Sa); add2(ra, ra, Da[j]);
                    ull rb = yb; fma2(rb, nlinv2, Sb); add2(rb, rb, Db[j]);
                    const float2 fa = unpack2(ra);
                    const float xa0 = copysignf(fmaxf(fabsf(fa.x) - lam, 0.f), fa.x);
                    const float xa1 = copysignf(fmaxf(fabsf(fa.y) - lam, 0.f), fa.y);
                    const float2 xoa = unpack2(xold[s][0][j]);
                    const float yna0 = fmaf(tt, xa0 - xoa.x, xa0);
                    const float yna1 = fmaf(tt, xa1 - xoa.y, xa1);
                    xold[s][0][j] = pack2(xa0, xa1);
                    const ull yna = pack2(yna0, yna1);
                    const float2 fb = unpack2(rb);
                    const float xb0 = copysignf(fmaxf(fabsf(fb.x) - lam, 0.f), fb.x);
                    const float xb1 = copysignf(fmaxf(fabsf(fb.y) - lam, 0.f), fb.y);
                    const float2 xob = unpack2(xold[s][1][j]);
                    const float ynb0 = fmaf(tt, xb0 - xob.x, xb0);
                    const float ynb1 = fmaf(tt, xb1 - xob.y, xb1);
                    xold[s][1][j] = pack2(xb0, xb1);
                    const ull ynb = pack2(ynb0, ynb1);
                    add2(pnew[j], yna, ynb);
                    mnew[j] = yna; fma2(mnew[j], neg1, ynb);
                }
                ulonglong2 p01; p01.x = pnew[0]; p01.y = pnew[1];
                ulonglong2 p23; p23.x = pnew[2]; p23.y = pnew[3];
                *(ulonglong2*)(Uprow)     = p01;
                *(ulonglong2*)(Uprow + 2) = p23;
                ulonglong2 m01; m01.x = mnew[0]; m01.y = mnew[1];
                ulonglong2 m23; m23.x = mnew[2]; m23.y = mnew[3];
                *(ulonglong2*)(Umrow)     = m01;
                *(ulonglong2*)(Umrow + 2) = m23;
            }
        } else if (isK0) {
            ull T[4] = {};
            #pragma unroll 6
            for (int t = 0; t < T36; ++t) {
                const ulonglong2 v01 = *(const ulonglong2*)(vP + t * SYS);
                const ulonglong2 v23 = *(const ulonglong2*)(vP + t * SYS + 2);
                add2(T[0], T[0], v01.x); add2(T[1], T[1], v01.y);
                add2(T[2], T[2], v23.x); add2(T[3], T[3], v23.y);
            }
            const ull* D0 = sDtY + (size_t)160 * SYS + 4 * pg;
            #pragma unroll
            for (int j = 0; j < 4; ++j) {
                ull S; mul2(S, T[j], invs2);
                ull r = y0r[j]; fma2(r, nlinv2, S); add2(r, r, D0[j]);
                const float2 fr = unpack2(r);
                const float x0 = copysignf(fmaxf(fabsf(fr.x) - lam, 0.f), fr.x);
                const float x1 = copysignf(fmaxf(fabsf(fr.y) - lam, 0.f), fr.y);
                const float2 xo = unpack2(x0r[j]);
                const float yn0 = fmaf(tt, x0 - xo.x, x0);
                const float yn1 = fmaf(tt, x1 - xo.y, x1);
                x0r[j] = pack2(x0, x1);
                y0r[j] = pack2(yn0, yn1);
                ull ys; mul2(ys, y0r[j], invs2);
                sY0[4 * pg + j] = ys;
            }
        }
        __syncthreads();
    }

    // ---- write final x (xold) straight to GMEM ----
    if (reg2) {
        #pragma unroll
        for (int s = 0; s < 2; ++s) {
            const int slot = 2 * ng + s;
            const int ka = (slot < 40) ? 1 + slot : 41 + slot;
            const int kb = ka + 40;
            #pragma unroll
            for (int j = 0; j < 4; ++j) {
                const int c0 = colBase + 8 * pg + 2 * j;
                if (c0 < TOTCOL) {
                    const int b = c0 / FDIM, f = c0 % FDIM;
                    *(float2*)(out + ((size_t)b * KOUT + ka) * FDIM + f) = unpack2(xold[s][0][j]);
                    *(float2*)(out + ((size_t)b * KOUT + kb) * FDIM + f) = unpack2(xold[s][1][j]);
                }
            }
        }
    } else if (isK0) {
        #pragma unroll
        for (int j = 0; j < 4; ++j) {
            const int c0 = colBase + 8 * pg + 2 * j;
            if (c0 < TOTCOL) {
                const int b = c0 / FDIM, f = c0 % FDIM;
                *(float2*)(out + ((size_t)b * KOUT + 0) * FDIM + f) = unpack2(x0r[j]);
            }
        }
    }
}

// =====================================================================
extern "C" void kernel_launch(void* const* d_in, const int* in_sizes, int n_in,
                              void* d_out, int out_size)
{
    const float* x   = (const float*)d_in[0];
    const float* drr = (const float*)d_in[1];
    const float* dth = (const float*)d_in[2];
    float* out = (float*)d_out;
    (void)in_sizes; (void)n_in; (void)out_size;

    const size_t smem = (size_t)(160 * SYS + 161 * SYS + TPAD * SYS + SYS + SAS * 48) * sizeof(ull)
                      + (size_t)(T36 * SAS) * sizeof(float);   // ~190.2 KB

    cudaFuncSetAttribute(dyan_fista_kernel,
                         cudaFuncAttributeMaxDynamicSharedMemorySize, (int)smem);

    dyan_setup_kernel<<<1, SETUP_T>>>(drr, dth);

    const int grid = (TOTCOL + NCOL - 1) / NCOL;   // 427
    dyan_fista_kernel<<<grid, NTHREADS, smem>>>(x, out);
}